// round 2
// baseline (speedup 1.0000x reference)
#include <cuda_runtime.h>
#include <cstdint>
#include <math.h>

#define B_SZ 4
#define T_SZ 2048
#define C_SZ 768
#define H_SZ 16
#define D_SZ 48
#define M_SZ (B_SZ * T_SZ)          // 8192

// Scratch (device globals: allocation-free rule)
__device__ float g_q[B_SZ * H_SZ * T_SZ * D_SZ];   // [bh][t][d]
__device__ float g_k[B_SZ * H_SZ * T_SZ * D_SZ];
__device__ float g_v[B_SZ * H_SZ * T_SZ * D_SZ];
__device__ float g_ctx[B_SZ * T_SZ * C_SZ];        // [b*t][c]

// ---------------------------------------------------------------------------
// GEMM: out[m,n] = sum_k A[m,k] * W[n,k] + bias[n]
// BM=BN=128, BK=8, 256 threads, 8x8 per-thread tile, double-buffered smem.
// SPLIT=true  -> scatter into [b*H+h][t][d] head-split layout
// SPLIT=false -> row-major [m][n]
// blockIdx.z selects (W, bias, out) triple -> fused QKV in one launch.
// ---------------------------------------------------------------------------
template<bool SPLIT>
__global__ __launch_bounds__(256)
void gemm_bias_kernel(const float* __restrict__ A,
                      const float* __restrict__ W0, const float* __restrict__ W1, const float* __restrict__ W2,
                      const float* __restrict__ b0, const float* __restrict__ b1, const float* __restrict__ b2,
                      float* o0, float* o1, float* o2)
{
    const float* W; const float* bias; float* O;
    if (blockIdx.z == 0)      { W = W0; bias = b0; O = o0; }
    else if (blockIdx.z == 1) { W = W1; bias = b1; O = o1; }
    else                      { W = W2; bias = b2; O = o2; }

    __shared__ __align__(16) float As[2][8][128];
    __shared__ __align__(16) float Bs[2][8][128];

    const int tid = threadIdx.x;
    const int tx = tid & 15;
    const int ty = tid >> 4;
    const int m0 = blockIdx.y * 128;
    const int n0 = blockIdx.x * 128;

    const int lrow = tid >> 1;          // 0..127
    const int lkc  = (tid & 1) * 4;     // 0 or 4

    const float* Aptr = A + (size_t)(m0 + lrow) * C_SZ + lkc;
    const float* Wptr = W + (size_t)(n0 + lrow) * C_SZ + lkc;

    float acc[8][8];
    #pragma unroll
    for (int i = 0; i < 8; ++i)
        #pragma unroll
        for (int j = 0; j < 8; ++j) acc[i][j] = 0.0f;

    // preload tile 0
    {
        float4 av = *(const float4*)Aptr;
        float4 bv = *(const float4*)Wptr;
        As[0][lkc+0][lrow] = av.x; As[0][lkc+1][lrow] = av.y;
        As[0][lkc+2][lrow] = av.z; As[0][lkc+3][lrow] = av.w;
        Bs[0][lkc+0][lrow] = bv.x; Bs[0][lkc+1][lrow] = bv.y;
        Bs[0][lkc+2][lrow] = bv.z; Bs[0][lkc+3][lrow] = bv.w;
    }
    __syncthreads();

    const int nk = C_SZ / 8;  // 96
    int buf = 0;
    for (int kt = 0; kt < nk; ++kt) {
        float4 av2, bv2;
        if (kt + 1 < nk) {
            av2 = *(const float4*)(Aptr + (kt + 1) * 8);
            bv2 = *(const float4*)(Wptr + (kt + 1) * 8);
        }
        #pragma unroll
        for (int k = 0; k < 8; ++k) {
            float4 a0 = *(const float4*)&As[buf][k][ty * 8];
            float4 a1 = *(const float4*)&As[buf][k][ty * 8 + 4];
            float4 bb0 = *(const float4*)&Bs[buf][k][tx * 8];
            float4 bb1 = *(const float4*)&Bs[buf][k][tx * 8 + 4];
            float ar[8] = {a0.x, a0.y, a0.z, a0.w, a1.x, a1.y, a1.z, a1.w};
            float br[8] = {bb0.x, bb0.y, bb0.z, bb0.w, bb1.x, bb1.y, bb1.z, bb1.w};
            #pragma unroll
            for (int i = 0; i < 8; ++i)
                #pragma unroll
                for (int j = 0; j < 8; ++j)
                    acc[i][j] += ar[i] * br[j];
        }
        if (kt + 1 < nk) {
            int nb = buf ^ 1;
            As[nb][lkc+0][lrow] = av2.x; As[nb][lkc+1][lrow] = av2.y;
            As[nb][lkc+2][lrow] = av2.z; As[nb][lkc+3][lrow] = av2.w;
            Bs[nb][lkc+0][lrow] = bv2.x; Bs[nb][lkc+1][lrow] = bv2.y;
            Bs[nb][lkc+2][lrow] = bv2.z; Bs[nb][lkc+3][lrow] = bv2.w;
        }
        __syncthreads();
        buf ^= 1;
    }

    // epilogue
    #pragma unroll
    for (int i = 0; i < 8; ++i) {
        const int m = m0 + ty * 8 + i;
        #pragma unroll
        for (int j = 0; j < 8; ++j) {
            const int n = n0 + tx * 8 + j;
            float v = acc[i][j] + bias[n];
            if (SPLIT) {
                int b = m >> 11;         // /T_SZ
                int t = m & (T_SZ - 1);
                int h = n / D_SZ;
                int d = n - h * D_SZ;
                O[(((size_t)(b * H_SZ + h)) * T_SZ + t) * D_SZ + d] = v;
            } else {
                O[(size_t)m * C_SZ + n] = v;
            }
        }
    }
}

// ---------------------------------------------------------------------------
// RoPE, in-place on Q and K ([bh][t][48] layout). One thread per (row, pair).
// ---------------------------------------------------------------------------
__global__ __launch_bounds__(256)
void rope_kernel(float* __restrict__ q, float* __restrict__ k)
{
    const int total = B_SZ * H_SZ * T_SZ * (D_SZ / 2);
    int idx = blockIdx.x * blockDim.x + threadIdx.x;
    if (idx >= total) return;
    int j   = idx % (D_SZ / 2);        // 0..23
    int row = idx / (D_SZ / 2);        // bh*T + t
    int t   = row & (T_SZ - 1);

    // inv_freq computed in double for accuracy, matching fp32 reference within ulps
    float inv = (float)exp(-log(10000.0) * (double)j / 24.0);
    float ang = (float)t * inv;
    float s, c;
    sincosf(ang, &s, &c);

    float* qp = q + (size_t)row * D_SZ;
    float q1 = qp[j], q2 = qp[j + 24];
    qp[j]      = q1 * c - q2 * s;
    qp[j + 24] = q2 * c + q1 * s;

    float* kp = k + (size_t)row * D_SZ;
    float k1 = kp[j], k2 = kp[j + 24];
    kp[j]      = k1 * c - k2 * s;
    kp[j + 24] = k2 * c + k1 * s;
}

// ---------------------------------------------------------------------------
// Flash attention, fp32. One thread per query row; K/V tiles of 64 in smem.
// Online softmax over 16-key chunks. Causal + additive padding mask.
// Writes ctx in [b*t][h*48+d] (row-major [M, C]) layout for the O-proj GEMM.
// ---------------------------------------------------------------------------
__global__ __launch_bounds__(128)
void attn_kernel(const float* __restrict__ Q, const float* __restrict__ K,
                 const float* __restrict__ V, const float* __restrict__ mask,
                 float* __restrict__ ctx)
{
    __shared__ __align__(16) float Ks[64 * D_SZ];
    __shared__ __align__(16) float Vs[64 * D_SZ];
    __shared__ float smadd[64];

    const int tid = threadIdx.x;
    const int bh = blockIdx.y;
    const int b = bh >> 4;
    const int h = bh & 15;
    const int i = blockIdx.x * 128 + tid;   // query row
    const float scale = 0.14433756729740643f;  // 1/sqrt(48)

    float4 q[12];
    {
        const float4* qp = (const float4*)(Q + ((size_t)bh * T_SZ + i) * D_SZ);
        #pragma unroll
        for (int r = 0; r < 12; ++r) q[r] = qp[r];
    }

    float4 acc[12];
    #pragma unroll
    for (int r = 0; r < 12; ++r) acc[r] = make_float4(0.f, 0.f, 0.f, 0.f);
    float mrow = -1e30f;
    float lsum = 0.0f;

    const int ntiles = blockIdx.x * 2 + 2;  // keys 0 .. base+127 covered
    for (int tile = 0; tile < ntiles; ++tile) {
        const int j0 = tile * 64;
        // cooperative tile load (rows are contiguous: 64*48 floats = 768 float4)
        {
            const float4* kg = (const float4*)(K + ((size_t)bh * T_SZ + j0) * D_SZ);
            const float4* vg = (const float4*)(V + ((size_t)bh * T_SZ + j0) * D_SZ);
            float4* ks4 = (float4*)Ks;
            float4* vs4 = (float4*)Vs;
            #pragma unroll
            for (int u = 0; u < 6; ++u) {
                ks4[tid + u * 128] = kg[tid + u * 128];
                vs4[tid + u * 128] = vg[tid + u * 128];
            }
            if (tid < 64)
                smadd[tid] = (1.0f - mask[b * T_SZ + j0 + tid]) * -10000.0f;
        }
        __syncthreads();

        #pragma unroll 1
        for (int c = 0; c < 4; ++c) {
            const int jb = j0 + c * 16;
            if (jb > i) break;   // later chunks only larger -> done with this tile
            float s[16];
            #pragma unroll
            for (int jj = 0; jj < 16; ++jj) {
                const float4* kr = (const float4*)&Ks[(c * 16 + jj) * D_SZ];
                float d0 = 0.f, d1 = 0.f, d2 = 0.f, d3 = 0.f;
                #pragma unroll
                for (int r = 0; r < 12; r += 4) {
                    float4 k0 = kr[r + 0], k1 = kr[r + 1], k2 = kr[r + 2], k3 = kr[r + 3];
                    d0 += q[r + 0].x * k0.x + q[r + 0].y * k0.y + q[r + 0].z * k0.z + q[r + 0].w * k0.w;
                    d1 += q[r + 1].x * k1.x + q[r + 1].y * k1.y + q[r + 1].z * k1.z + q[r + 1].w * k1.w;
                    d2 += q[r + 2].x * k2.x + q[r + 2].y * k2.y + q[r + 2].z * k2.z + q[r + 2].w * k2.w;
                    d3 += q[r + 3].x * k3.x + q[r + 3].y * k3.y + q[r + 3].z * k3.z + q[r + 3].w * k3.w;
                }
                float dot = (d0 + d1) + (d2 + d3);
                float sv = dot * scale + smadd[c * 16 + jj];
                s[jj] = (jb + jj <= i) ? sv : -1e30f;
            }
            float cmax = s[0];
            #pragma unroll
            for (int jj = 1; jj < 16; ++jj) cmax = fmaxf(cmax, s[jj]);
            float mnew = fmaxf(mrow, cmax);
            float alpha = __expf(mrow - mnew);
            lsum *= alpha;
            #pragma unroll
            for (int r = 0; r < 12; ++r) {
                acc[r].x *= alpha; acc[r].y *= alpha;
                acc[r].z *= alpha; acc[r].w *= alpha;
            }
            #pragma unroll
            for (int jj = 0; jj < 16; ++jj) {
                float p = __expf(s[jj] - mnew);
                lsum += p;
                const float4* vr = (const float4*)&Vs[(c * 16 + jj) * D_SZ];
                #pragma unroll
                for (int r = 0; r < 12; ++r) {
                    float4 vv = vr[r];
                    acc[r].x += p * vv.x; acc[r].y += p * vv.y;
                    acc[r].z += p * vv.z; acc[r].w += p * vv.w;
                }
            }
            mrow = mnew;
        }
        __syncthreads();
    }

    const float inv = 1.0f / lsum;
    float4* op = (float4*)(ctx + ((size_t)(b * T_SZ + i)) * C_SZ + h * D_SZ);
    #pragma unroll
    for (int r = 0; r < 12; ++r) {
        float4 o;
        o.x = acc[r].x * inv; o.y = acc[r].y * inv;
        o.z = acc[r].z * inv; o.w = acc[r].w * inv;
        op[r] = o;
    }
}

// ---------------------------------------------------------------------------
extern "C" void kernel_launch(void* const* d_in, const int* in_sizes, int n_in,
                              void* d_out, int out_size)
{
    const float* hs    = (const float*)d_in[0];
    const float* amask = (const float*)d_in[1];
    const float* Wq = (const float*)d_in[2]; const float* bq = (const float*)d_in[3];
    const float* Wk = (const float*)d_in[4]; const float* bk = (const float*)d_in[5];
    const float* Wv = (const float*)d_in[6]; const float* bv = (const float*)d_in[7];
    const float* Wo = (const float*)d_in[8]; const float* bo = (const float*)d_in[9];
    float* out = (float*)d_out;

    float *q_ptr, *k_ptr, *v_ptr, *ctx_ptr;
    cudaGetSymbolAddress((void**)&q_ptr,   g_q);
    cudaGetSymbolAddress((void**)&k_ptr,   g_k);
    cudaGetSymbolAddress((void**)&v_ptr,   g_v);
    cudaGetSymbolAddress((void**)&ctx_ptr, g_ctx);

    // 1. Fused QKV projections -> head-split layouts
    dim3 g1(C_SZ / 128, M_SZ / 128, 3);
    gemm_bias_kernel<true><<<g1, 256>>>(hs, Wq, Wk, Wv, bq, bk, bv,
                                        q_ptr, k_ptr, v_ptr);

    // 2. RoPE in place on Q, K
    const int rope_total = B_SZ * H_SZ * T_SZ * (D_SZ / 2);
    rope_kernel<<<(rope_total + 255) / 256, 256>>>(q_ptr, k_ptr);

    // 3. Causal flash attention -> ctx [M, C]
    attn_kernel<<<dim3(T_SZ / 128, B_SZ * H_SZ), 128>>>(q_ptr, k_ptr, v_ptr,
                                                        amask, ctx_ptr);

    // 4. Output projection -> d_out
    dim3 g4(C_SZ / 128, M_SZ / 128, 1);
    gemm_bias_kernel<false><<<g4, 256>>>(ctx_ptr, Wo, Wo, Wo, bo, bo, bo,
                                         out, out, out);
}

// round 7
// speedup vs baseline: 1.2146x; 1.2146x over previous
#include <cuda_runtime.h>
#include <cstdint>
#include <math.h>

#define B_SZ 4
#define T_SZ 2048
#define C_SZ 768
#define H_SZ 16
#define D_SZ 48
#define M_SZ (B_SZ * T_SZ)          // 8192

// Scratch (device globals: allocation-free rule)
__device__ float g_q[B_SZ * H_SZ * T_SZ * D_SZ];   // [bh][t][d]
__device__ float g_k[B_SZ * H_SZ * T_SZ * D_SZ];
__device__ float g_v[B_SZ * H_SZ * T_SZ * D_SZ];
__device__ float g_ctx[B_SZ * T_SZ * C_SZ];        // [b*t][c]

// ===========================================================================
// mma.sync bf16 (baseline PTX, works on plain sm_103 target -> HMMA SASS)
// D(16x8,f32) += A(16x16,bf16) * B(16x8,bf16)^T-ish (row.col)
// ===========================================================================
__device__ __forceinline__ void mma_bf16(float* d, const uint32_t* a, const uint32_t* b)
{
    asm volatile(
        "mma.sync.aligned.m16n8k16.row.col.f32.bf16.bf16.f32 "
        "{%0,%1,%2,%3}, {%4,%5,%6,%7}, {%8,%9}, {%0,%1,%2,%3};"
        : "+f"(d[0]), "+f"(d[1]), "+f"(d[2]), "+f"(d[3])
        : "r"(a[0]), "r"(a[1]), "r"(a[2]), "r"(a[3]), "r"(b[0]), "r"(b[1]));
}

// ===========================================================================
// Split-precision bf16 tensor-core GEMM:
//   out[m,n] = sum_k A[m,k] * W[n,k] + bias[n]
// fp32 = bf16_hi + bf16_lo;  product = hi*hi + hi*lo + lo*hi  (err ~2^-19)
// Tile: BM=128, BN=128, BK=32. 256 threads = 8 warps (2 x 4), warp tile 64x32.
// smem: 4 tiles (Ahi, Alo, Bhi, Blo) of [128][40] bf16 (stride 80B = 20 banks
// -> conflict-free fragment loads). Register-prefetch of next K-block.
// blockIdx.z selects (W,bias,out) triple -> fused QKV in one launch.
// SPLIT=true scatters into [b*H+h][t][d]; else row-major [m][n].
// ===========================================================================
#define SKP 40                      // bf16 elems per smem row (80 B stride)
#define NKB (C_SZ / 32)             // 24 K-blocks

template<bool SPLIT>
__global__ __launch_bounds__(256, 1)
void gemm_mma_kernel(const float* __restrict__ A,
                     const float* __restrict__ W0, const float* __restrict__ W1, const float* __restrict__ W2,
                     const float* __restrict__ b0, const float* __restrict__ b1, const float* __restrict__ b2,
                     float* o0, float* o1, float* o2)
{
    const float* W; const float* bias; float* O;
    if (blockIdx.z == 0)      { W = W0; bias = b0; O = o0; }
    else if (blockIdx.z == 1) { W = W1; bias = b1; O = o1; }
    else                      { W = W2; bias = b2; O = o2; }

    // [0]=Ahi [1]=Alo [2]=Bhi [3]=Blo
    __shared__ __align__(16) uint16_t sm[4][128 * SKP];

    const int tid  = threadIdx.x;
    const int wid  = tid >> 5;
    const int lane = tid & 31;
    const int warp_m = wid & 1;      // 0..1
    const int warp_n = wid >> 1;     // 0..3
    const int m0 = blockIdx.y * 128;
    const int n0 = blockIdx.x * 128;

    // ---- load/convert duty: thread t handles row t>>1, half t&1 (16 floats)
    const int row = tid >> 1;
    const int hf  = tid & 1;
    const float* Asrc = A + (size_t)(m0 + row) * C_SZ + hf * 16;
    const float* Bsrc = W + (size_t)(n0 + row) * C_SZ + hf * 16;

    float4 pa[4], pb[4];

    auto fetch = [&](int kb) {
        #pragma unroll
        for (int q = 0; q < 4; ++q) {
            pa[q] = *(const float4*)(Asrc + kb * 32 + q * 4);
            pb[q] = *(const float4*)(Bsrc + kb * 32 + q * 4);
        }
    };

    auto cvst = [&]() {
        #pragma unroll
        for (int q = 0; q < 4; ++q) {
            const uint32_t boff = (uint32_t)(row * 80 + (hf * 16 + q * 4) * 2);
            {
                float4 v = pa[q];
                uint32_t h0, h1, l0, l1;
                asm("cvt.rn.bf16x2.f32 %0, %1, %2;" : "=r"(h0) : "f"(v.y), "f"(v.x));
                asm("cvt.rn.bf16x2.f32 %0, %1, %2;" : "=r"(h1) : "f"(v.w), "f"(v.z));
                float r0 = v.x - __uint_as_float(h0 << 16);
                float r1 = v.y - __uint_as_float(h0 & 0xFFFF0000u);
                float r2 = v.z - __uint_as_float(h1 << 16);
                float r3 = v.w - __uint_as_float(h1 & 0xFFFF0000u);
                asm("cvt.rn.bf16x2.f32 %0, %1, %2;" : "=r"(l0) : "f"(r1), "f"(r0));
                asm("cvt.rn.bf16x2.f32 %0, %1, %2;" : "=r"(l1) : "f"(r3), "f"(r2));
                *(uint2*)((char*)sm[0] + boff) = make_uint2(h0, h1);
                *(uint2*)((char*)sm[1] + boff) = make_uint2(l0, l1);
            }
            {
                float4 v = pb[q];
                uint32_t h0, h1, l0, l1;
                asm("cvt.rn.bf16x2.f32 %0, %1, %2;" : "=r"(h0) : "f"(v.y), "f"(v.x));
                asm("cvt.rn.bf16x2.f32 %0, %1, %2;" : "=r"(h1) : "f"(v.w), "f"(v.z));
                float r0 = v.x - __uint_as_float(h0 << 16);
                float r1 = v.y - __uint_as_float(h0 & 0xFFFF0000u);
                float r2 = v.z - __uint_as_float(h1 << 16);
                float r3 = v.w - __uint_as_float(h1 & 0xFFFF0000u);
                asm("cvt.rn.bf16x2.f32 %0, %1, %2;" : "=r"(l0) : "f"(r1), "f"(r0));
                asm("cvt.rn.bf16x2.f32 %0, %1, %2;" : "=r"(l1) : "f"(r3), "f"(r2));
                *(uint2*)((char*)sm[2] + boff) = make_uint2(h0, h1);
                *(uint2*)((char*)sm[3] + boff) = make_uint2(l0, l1);
            }
        }
    };

    float acc[16][4];
    #pragma unroll
    for (int i = 0; i < 16; ++i)
        #pragma unroll
        for (int j = 0; j < 4; ++j) acc[i][j] = 0.0f;

    const int g  = lane >> 2;
    const int tc = lane & 3;
    // per-thread fragment base byte offsets within a tile
    const uint32_t a_off = (uint32_t)((warp_m * 64 + g) * 80 + tc * 4);
    const uint32_t b_off = (uint32_t)((warp_n * 32 + g) * 80 + tc * 4);

    fetch(0);
    cvst();
    __syncthreads();

    for (int kb = 0; kb < NKB; ++kb) {
        if (kb + 1 < NKB) fetch(kb + 1);

        #pragma unroll
        for (int ks = 0; ks < 2; ++ks) {
            uint32_t ahi[4][4], alo[4][4], bhi[4][2], blo[4][2];
            #pragma unroll
            for (int mt = 0; mt < 4; ++mt) {
                const uint32_t o = a_off + (uint32_t)(mt * 16 * 80 + ks * 32);
                const char* ph = (const char*)sm[0] + o;
                const char* pl = (const char*)sm[1] + o;
                ahi[mt][0] = *(const uint32_t*)ph;
                ahi[mt][1] = *(const uint32_t*)(ph + 8 * 80);
                ahi[mt][2] = *(const uint32_t*)(ph + 16);
                ahi[mt][3] = *(const uint32_t*)(ph + 8 * 80 + 16);
                alo[mt][0] = *(const uint32_t*)pl;
                alo[mt][1] = *(const uint32_t*)(pl + 8 * 80);
                alo[mt][2] = *(const uint32_t*)(pl + 16);
                alo[mt][3] = *(const uint32_t*)(pl + 8 * 80 + 16);
            }
            #pragma unroll
            for (int nt = 0; nt < 4; ++nt) {
                const uint32_t o = b_off + (uint32_t)(nt * 8 * 80 + ks * 32);
                const char* ph = (const char*)sm[2] + o;
                const char* pl = (const char*)sm[3] + o;
                bhi[nt][0] = *(const uint32_t*)ph;
                bhi[nt][1] = *(const uint32_t*)(ph + 16);
                blo[nt][0] = *(const uint32_t*)pl;
                blo[nt][1] = *(const uint32_t*)(pl + 16);
            }
            #pragma unroll
            for (int mt = 0; mt < 4; ++mt)
                #pragma unroll
                for (int nt = 0; nt < 4; ++nt) {
                    mma_bf16(acc[mt * 4 + nt], ahi[mt], bhi[nt]);
                    mma_bf16(acc[mt * 4 + nt], ahi[mt], blo[nt]);
                    mma_bf16(acc[mt * 4 + nt], alo[mt], bhi[nt]);
                }
        }
        __syncthreads();
        if (kb + 1 < NKB) {
            cvst();
            __syncthreads();
        }
    }

    // ---- epilogue: acc fragment (mt,nt): rows m0+warp_m*64+mt*16+g(+8),
    //      cols n0+warp_n*32+nt*8+tc*2 (+1)
    #pragma unroll
    for (int mt = 0; mt < 4; ++mt) {
        const int rm = m0 + warp_m * 64 + mt * 16 + g;
        #pragma unroll
        for (int nt = 0; nt < 4; ++nt) {
            const int n = n0 + warp_n * 32 + nt * 8 + tc * 2;
            const float* ac = acc[mt * 4 + nt];
            float bv0 = __ldg(bias + n), bv1 = __ldg(bias + n + 1);
            if (SPLIT) {
                #pragma unroll
                for (int e = 0; e < 4; ++e) {
                    int m = rm + (e >> 1) * 8;
                    int nn = n + (e & 1);
                    float v = ac[e] + ((e & 1) ? bv1 : bv0);
                    int b = m >> 11;
                    int t = m & (T_SZ - 1);
                    int h = nn / D_SZ;
                    int d = nn - h * D_SZ;
                    O[(((size_t)(b * H_SZ + h)) * T_SZ + t) * D_SZ + d] = v;
                }
            } else {
                *(float2*)(O + (size_t)rm * C_SZ + n)       = make_float2(ac[0] + bv0, ac[1] + bv1);
                *(float2*)(O + (size_t)(rm + 8) * C_SZ + n) = make_float2(ac[2] + bv0, ac[3] + bv1);
            }
        }
    }
}

// ---------------------------------------------------------------------------
// RoPE, in-place on Q and K ([bh][t][48] layout). One thread per (row, pair).
// ---------------------------------------------------------------------------
__global__ __launch_bounds__(256)
void rope_kernel(float* __restrict__ q, float* __restrict__ k)
{
    const int total = B_SZ * H_SZ * T_SZ * (D_SZ / 2);
    int idx = blockIdx.x * blockDim.x + threadIdx.x;
    if (idx >= total) return;
    int j   = idx % (D_SZ / 2);        // 0..23
    int row = idx / (D_SZ / 2);        // bh*T + t
    int t   = row & (T_SZ - 1);

    float inv = (float)exp(-log(10000.0) * (double)j / 24.0);
    float ang = (float)t * inv;
    float s, c;
    sincosf(ang, &s, &c);

    float* qp = q + (size_t)row * D_SZ;
    float q1 = qp[j], q2 = qp[j + 24];
    qp[j]      = q1 * c - q2 * s;
    qp[j + 24] = q2 * c + q1 * s;

    float* kp = k + (size_t)row * D_SZ;
    float k1 = kp[j], k2 = kp[j + 24];
    kp[j]      = k1 * c - k2 * s;
    kp[j + 24] = k2 * c + k1 * s;
}

// ---------------------------------------------------------------------------
// Fast exp on the FMA pipe (no MUFU): exp(x) = 2^(x*log2e), poly on [-0.5,0.5]
// ---------------------------------------------------------------------------
__device__ __forceinline__ float fast_exp(float x)
{
    float y = fmaxf(x * 1.4426950408889634f, -126.0f);
    float r = y + 12582912.0f;                       // round to nearest int
    int   n = __float_as_int(r) - 0x4B400000;
    float f = y - (r - 12582912.0f);                 // f in [-0.5, 0.5]
    float p = 1.33978852e-3f;
    p = fmaf(p, f, 9.61843737e-3f);
    p = fmaf(p, f, 5.55033247e-2f);
    p = fmaf(p, f, 2.40226479e-1f);
    p = fmaf(p, f, 6.93147203e-1f);
    p = fmaf(p, f, 1.0f);
    return __int_as_float(__float_as_int(p) + (n << 23));
}

// ---------------------------------------------------------------------------
// Flash attention, fp32. One thread per query row; K/V tiles of 64 in smem.
// ---------------------------------------------------------------------------
__global__ __launch_bounds__(128)
void attn_kernel(const float* __restrict__ Q, const float* __restrict__ K,
                 const float* __restrict__ V, const float* __restrict__ mask,
                 float* __restrict__ ctx)
{
    __shared__ __align__(16) float Ks[64 * D_SZ];
    __shared__ __align__(16) float Vs[64 * D_SZ];
    __shared__ float smadd[64];

    const int tid = threadIdx.x;
    const int bh = blockIdx.y;
    const int b = bh >> 4;
    const int h = bh & 15;
    const int i = blockIdx.x * 128 + tid;   // query row
    const float scale = 0.14433756729740643f;  // 1/sqrt(48)

    float4 q[12];
    {
        const float4* qp = (const float4*)(Q + ((size_t)bh * T_SZ + i) * D_SZ);
        #pragma unroll
        for (int r = 0; r < 12; ++r) q[r] = qp[r];
    }

    float4 acc[12];
    #pragma unroll
    for (int r = 0; r < 12; ++r) acc[r] = make_float4(0.f, 0.f, 0.f, 0.f);
    float mrow = -1e30f;
    float lsum = 0.0f;

    const int ntiles = blockIdx.x * 2 + 2;
    for (int tile = 0; tile < ntiles; ++tile) {
        const int j0 = tile * 64;
        {
            const float4* kg = (const float4*)(K + ((size_t)bh * T_SZ + j0) * D_SZ);
            const float4* vg = (const float4*)(V + ((size_t)bh * T_SZ + j0) * D_SZ);
            float4* ks4 = (float4*)Ks;
            float4* vs4 = (float4*)Vs;
            #pragma unroll
            for (int u = 0; u < 6; ++u) {
                ks4[tid + u * 128] = kg[tid + u * 128];
                vs4[tid + u * 128] = vg[tid + u * 128];
            }
            if (tid < 64)
                smadd[tid] = (1.0f - mask[b * T_SZ + j0 + tid]) * -10000.0f;
        }
        __syncthreads();

        #pragma unroll 1
        for (int c = 0; c < 4; ++c) {
            const int jb = j0 + c * 16;
            if (jb > i) break;
            float s[16];
            #pragma unroll
            for (int jj = 0; jj < 16; ++jj) {
                const float4* kr = (const float4*)&Ks[(c * 16 + jj) * D_SZ];
                float d0 = 0.f, d1 = 0.f, d2 = 0.f, d3 = 0.f;
                #pragma unroll
                for (int r = 0; r < 12; r += 4) {
                    float4 k0 = kr[r + 0], k1 = kr[r + 1], k2 = kr[r + 2], k3 = kr[r + 3];
                    d0 += q[r + 0].x * k0.x + q[r + 0].y * k0.y + q[r + 0].z * k0.z + q[r + 0].w * k0.w;
                    d1 += q[r + 1].x * k1.x + q[r + 1].y * k1.y + q[r + 1].z * k1.z + q[r + 1].w * k1.w;
                    d2 += q[r + 2].x * k2.x + q[r + 2].y * k2.y + q[r + 2].z * k2.z + q[r + 2].w * k2.w;
                    d3 += q[r + 3].x * k3.x + q[r + 3].y * k3.y + q[r + 3].z * k3.z + q[r + 3].w * k3.w;
                }
                float dot = (d0 + d1) + (d2 + d3);
                float sv = dot * scale + smadd[c * 16 + jj];
                s[jj] = (jb + jj <= i) ? sv : -1e30f;
            }
            float cmax = s[0];
            #pragma unroll
            for (int jj = 1; jj < 16; ++jj) cmax = fmaxf(cmax, s[jj]);
            float mnew = fmaxf(mrow, cmax);
            float alpha = fast_exp(mrow - mnew);
            lsum *= alpha;
            #pragma unroll
            for (int r = 0; r < 12; ++r) {
                acc[r].x *= alpha; acc[r].y *= alpha;
                acc[r].z *= alpha; acc[r].w *= alpha;
            }
            #pragma unroll
            for (int jj = 0; jj < 16; ++jj) {
                float p = fast_exp(s[jj] - mnew);
                lsum += p;
                const float4* vr = (const float4*)&Vs[(c * 16 + jj) * D_SZ];
                #pragma unroll
                for (int r = 0; r < 12; ++r) {
                    float4 vv = vr[r];
                    acc[r].x += p * vv.x; acc[r].y += p * vv.y;
                    acc[r].z += p * vv.z; acc[r].w += p * vv.w;
                }
            }
            mrow = mnew;
        }
        __syncthreads();
    }

    const float inv = 1.0f / lsum;
    float4* op = (float4*)(ctx + ((size_t)(b * T_SZ + i)) * C_SZ + h * D_SZ);
    #pragma unroll
    for (int r = 0; r < 12; ++r) {
        float4 o;
        o.x = acc[r].x * inv; o.y = acc[r].y * inv;
        o.z = acc[r].z * inv; o.w = acc[r].w * inv;
        op[r] = o;
    }
}

// ---------------------------------------------------------------------------
extern "C" void kernel_launch(void* const* d_in, const int* in_sizes, int n_in,
                              void* d_out, int out_size)
{
    const float* hs    = (const float*)d_in[0];
    const float* amask = (const float*)d_in[1];
    const float* Wq = (const float*)d_in[2]; const float* bq = (const float*)d_in[3];
    const float* Wk = (const float*)d_in[4]; const float* bk = (const float*)d_in[5];
    const float* Wv = (const float*)d_in[6]; const float* bv = (const float*)d_in[7];
    const float* Wo = (const float*)d_in[8]; const float* bo = (const float*)d_in[9];
    float* out = (float*)d_out;

    float *q_ptr, *k_ptr, *v_ptr, *ctx_ptr;
    cudaGetSymbolAddress((void**)&q_ptr,   g_q);
    cudaGetSymbolAddress((void**)&k_ptr,   g_k);
    cudaGetSymbolAddress((void**)&v_ptr,   g_v);
    cudaGetSymbolAddress((void**)&ctx_ptr, g_ctx);

    // 1. Fused QKV projections -> head-split layouts (tensor cores)
    dim3 g1(C_SZ / 128, M_SZ / 128, 3);
    gemm_mma_kernel<true><<<g1, 256>>>(hs, Wq, Wk, Wv, bq, bk, bv,
                                       q_ptr, k_ptr, v_ptr);

    // 2. RoPE in place on Q, K
    const int rope_total = B_SZ * H_SZ * T_SZ * (D_SZ / 2);
    rope_kernel<<<(rope_total + 255) / 256, 256>>>(q_ptr, k_ptr);

    // 3. Causal flash attention -> ctx [M, C]
    attn_kernel<<<dim3(T_SZ / 128, B_SZ * H_SZ), 128>>>(q_ptr, k_ptr, v_ptr,
                                                        amask, ctx_ptr);

    // 4. Output projection -> d_out (tensor cores)
    dim3 g4(C_SZ / 128, M_SZ / 128, 1);
    gemm_mma_kernel<false><<<g4, 256>>>(ctx_ptr, Wo, Wo, Wo, bo, bo, bo,
                                        out, out, out);
}

// round 9
// speedup vs baseline: 2.0202x; 1.6633x over previous
#include <cuda_runtime.h>
#include <cstdint>
#include <math.h>

#define B_SZ 4
#define T_SZ 2048
#define C_SZ 768
#define H_SZ 16
#define D_SZ 48
#define M_SZ (B_SZ * T_SZ)          // 8192

// Scratch (device globals: allocation-free rule)
__device__ float g_q[B_SZ * H_SZ * T_SZ * D_SZ];   // [bh][t][d]
__device__ float g_k[B_SZ * H_SZ * T_SZ * D_SZ];
__device__ float g_v[B_SZ * H_SZ * T_SZ * D_SZ];
__device__ float g_ctx[B_SZ * T_SZ * C_SZ];        // [b*t][c]

// ===========================================================================
// mma.sync bf16 (baseline PTX -> HMMA SASS on sm_103)
// ===========================================================================
__device__ __forceinline__ void mma_bf16(float* d, const uint32_t* a, const uint32_t* b)
{
    asm volatile(
        "mma.sync.aligned.m16n8k16.row.col.f32.bf16.bf16.f32 "
        "{%0,%1,%2,%3}, {%4,%5,%6,%7}, {%8,%9}, {%0,%1,%2,%3};"
        : "+f"(d[0]), "+f"(d[1]), "+f"(d[2]), "+f"(d[3])
        : "r"(a[0]), "r"(a[1]), "r"(a[2]), "r"(a[3]), "r"(b[0]), "r"(b[1]));
}

__device__ __forceinline__ uint32_t smem_u32(const void* p) {
    uint32_t a;
    asm("{ .reg .u64 t; cvta.to.shared.u64 t, %1; cvt.u32.u64 %0, t; }" : "=r"(a) : "l"(p));
    return a;
}

#define LDSM_X2_T(r0, r1, addr) \
    asm volatile("ldmatrix.sync.aligned.m8n8.x2.trans.shared.b16 {%0,%1}, [%2];" \
                 : "=r"(r0), "=r"(r1) : "r"(addr))

// split fp32 pair -> bf16x2 hi + bf16x2 lo
__device__ __forceinline__ void pack_pair(uint32_t& hi, uint32_t& lo, float x0, float x1)
{
    asm("cvt.rn.bf16x2.f32 %0, %1, %2;" : "=r"(hi) : "f"(x1), "f"(x0));
    float r0 = x0 - __uint_as_float(hi << 16);
    float r1 = x1 - __uint_as_float(hi & 0xFFFF0000u);
    asm("cvt.rn.bf16x2.f32 %0, %1, %2;" : "=r"(lo) : "f"(r1), "f"(r0));
}

__device__ __forceinline__ void convert4(float4 v, uint2& h, uint2& l)
{
    uint32_t h0, h1, l0, l1;
    asm("cvt.rn.bf16x2.f32 %0, %1, %2;" : "=r"(h0) : "f"(v.y), "f"(v.x));
    asm("cvt.rn.bf16x2.f32 %0, %1, %2;" : "=r"(h1) : "f"(v.w), "f"(v.z));
    float r0 = v.x - __uint_as_float(h0 << 16);
    float r1 = v.y - __uint_as_float(h0 & 0xFFFF0000u);
    float r2 = v.z - __uint_as_float(h1 << 16);
    float r3 = v.w - __uint_as_float(h1 & 0xFFFF0000u);
    asm("cvt.rn.bf16x2.f32 %0, %1, %2;" : "=r"(l0) : "f"(r1), "f"(r0));
    asm("cvt.rn.bf16x2.f32 %0, %1, %2;" : "=r"(l1) : "f"(r3), "f"(r2));
    h = make_uint2(h0, h1);
    l = make_uint2(l0, l1);
}

// ===========================================================================
// Split-precision bf16 tensor-core GEMM (validated R7): out = A*W^T + bias
// ===========================================================================
#define SKP 40
#define NKB (C_SZ / 32)

template<bool SPLIT>
__global__ __launch_bounds__(256, 1)
void gemm_mma_kernel(const float* __restrict__ A,
                     const float* __restrict__ W0, const float* __restrict__ W1, const float* __restrict__ W2,
                     const float* __restrict__ b0, const float* __restrict__ b1, const float* __restrict__ b2,
                     float* o0, float* o1, float* o2)
{
    const float* W; const float* bias; float* O;
    if (blockIdx.z == 0)      { W = W0; bias = b0; O = o0; }
    else if (blockIdx.z == 1) { W = W1; bias = b1; O = o1; }
    else                      { W = W2; bias = b2; O = o2; }

    __shared__ __align__(16) uint16_t sm[4][128 * SKP];

    const int tid  = threadIdx.x;
    const int wid  = tid >> 5;
    const int lane = tid & 31;
    const int warp_m = wid & 1;
    const int warp_n = wid >> 1;
    const int m0 = blockIdx.y * 128;
    const int n0 = blockIdx.x * 128;

    const int row = tid >> 1;
    const int hf  = tid & 1;
    const float* Asrc = A + (size_t)(m0 + row) * C_SZ + hf * 16;
    const float* Bsrc = W + (size_t)(n0 + row) * C_SZ + hf * 16;

    float4 pa[4], pb[4];

    auto fetch = [&](int kb) {
        #pragma unroll
        for (int q = 0; q < 4; ++q) {
            pa[q] = *(const float4*)(Asrc + kb * 32 + q * 4);
            pb[q] = *(const float4*)(Bsrc + kb * 32 + q * 4);
        }
    };

    auto cvst = [&]() {
        #pragma unroll
        for (int q = 0; q < 4; ++q) {
            const uint32_t boff = (uint32_t)(row * 80 + (hf * 16 + q * 4) * 2);
            uint2 h, l;
            convert4(pa[q], h, l);
            *(uint2*)((char*)sm[0] + boff) = h;
            *(uint2*)((char*)sm[1] + boff) = l;
            convert4(pb[q], h, l);
            *(uint2*)((char*)sm[2] + boff) = h;
            *(uint2*)((char*)sm[3] + boff) = l;
        }
    };

    float acc[16][4];
    #pragma unroll
    for (int i = 0; i < 16; ++i)
        #pragma unroll
        for (int j = 0; j < 4; ++j) acc[i][j] = 0.0f;

    const int g  = lane >> 2;
    const int tc = lane & 3;
    const uint32_t a_off = (uint32_t)((warp_m * 64 + g) * 80 + tc * 4);
    const uint32_t b_off = (uint32_t)((warp_n * 32 + g) * 80 + tc * 4);

    fetch(0);
    cvst();
    __syncthreads();

    for (int kb = 0; kb < NKB; ++kb) {
        if (kb + 1 < NKB) fetch(kb + 1);

        #pragma unroll
        for (int ks = 0; ks < 2; ++ks) {
            uint32_t ahi[4][4], alo[4][4], bhi[4][2], blo[4][2];
            #pragma unroll
            for (int mt = 0; mt < 4; ++mt) {
                const uint32_t o = a_off + (uint32_t)(mt * 16 * 80 + ks * 32);
                const char* ph = (const char*)sm[0] + o;
                const char* pl = (const char*)sm[1] + o;
                ahi[mt][0] = *(const uint32_t*)ph;
                ahi[mt][1] = *(const uint32_t*)(ph + 8 * 80);
                ahi[mt][2] = *(const uint32_t*)(ph + 16);
                ahi[mt][3] = *(const uint32_t*)(ph + 8 * 80 + 16);
                alo[mt][0] = *(const uint32_t*)pl;
                alo[mt][1] = *(const uint32_t*)(pl + 8 * 80);
                alo[mt][2] = *(const uint32_t*)(pl + 16);
                alo[mt][3] = *(const uint32_t*)(pl + 8 * 80 + 16);
            }
            #pragma unroll
            for (int nt = 0; nt < 4; ++nt) {
                const uint32_t o = b_off + (uint32_t)(nt * 8 * 80 + ks * 32);
                const char* ph = (const char*)sm[2] + o;
                const char* pl = (const char*)sm[3] + o;
                bhi[nt][0] = *(const uint32_t*)ph;
                bhi[nt][1] = *(const uint32_t*)(ph + 16);
                blo[nt][0] = *(const uint32_t*)pl;
                blo[nt][1] = *(const uint32_t*)(pl + 16);
            }
            #pragma unroll
            for (int mt = 0; mt < 4; ++mt)
                #pragma unroll
                for (int nt = 0; nt < 4; ++nt) {
                    mma_bf16(acc[mt * 4 + nt], ahi[mt], bhi[nt]);
                    mma_bf16(acc[mt * 4 + nt], ahi[mt], blo[nt]);
                    mma_bf16(acc[mt * 4 + nt], alo[mt], bhi[nt]);
                }
        }
        __syncthreads();
        if (kb + 1 < NKB) {
            cvst();
            __syncthreads();
        }
    }

    #pragma unroll
    for (int mt = 0; mt < 4; ++mt) {
        const int rm = m0 + warp_m * 64 + mt * 16 + g;
        #pragma unroll
        for (int nt = 0; nt < 4; ++nt) {
            const int n = n0 + warp_n * 32 + nt * 8 + tc * 2;
            const float* ac = acc[mt * 4 + nt];
            float bv0 = __ldg(bias + n), bv1 = __ldg(bias + n + 1);
            if (SPLIT) {
                #pragma unroll
                for (int e = 0; e < 4; ++e) {
                    int m = rm + (e >> 1) * 8;
                    int nn = n + (e & 1);
                    float v = ac[e] + ((e & 1) ? bv1 : bv0);
                    int b = m >> 11;
                    int t = m & (T_SZ - 1);
                    int h = nn / D_SZ;
                    int d = nn - h * D_SZ;
                    O[(((size_t)(b * H_SZ + h)) * T_SZ + t) * D_SZ + d] = v;
                }
            } else {
                *(float2*)(O + (size_t)rm * C_SZ + n)       = make_float2(ac[0] + bv0, ac[1] + bv1);
                *(float2*)(O + (size_t)(rm + 8) * C_SZ + n) = make_float2(ac[2] + bv0, ac[3] + bv1);
            }
        }
    }
}

// ---------------------------------------------------------------------------
// RoPE, in-place on Q and K ([bh][t][48] layout)
// ---------------------------------------------------------------------------
__global__ __launch_bounds__(256)
void rope_kernel(float* __restrict__ q, float* __restrict__ k)
{
    const int total = B_SZ * H_SZ * T_SZ * (D_SZ / 2);
    int idx = blockIdx.x * blockDim.x + threadIdx.x;
    if (idx >= total) return;
    int j   = idx % (D_SZ / 2);
    int row = idx / (D_SZ / 2);
    int t   = row & (T_SZ - 1);

    float inv = (float)exp(-log(10000.0) * (double)j / 24.0);
    float ang = (float)t * inv;
    float s, c;
    sincosf(ang, &s, &c);

    float* qp = q + (size_t)row * D_SZ;
    float q1 = qp[j], q2 = qp[j + 24];
    qp[j]      = q1 * c - q2 * s;
    qp[j + 24] = q2 * c + q1 * s;

    float* kp = k + (size_t)row * D_SZ;
    float k1 = kp[j], k2 = kp[j + 24];
    kp[j]      = k1 * c - k2 * s;
    kp[j + 24] = k2 * c + k1 * s;
}

// ---------------------------------------------------------------------------
// Fast exp on the FMA pipe
// ---------------------------------------------------------------------------
__device__ __forceinline__ float fast_exp(float x)
{
    float y = fmaxf(x * 1.4426950408889634f, -126.0f);
    float r = y + 12582912.0f;
    int   n = __float_as_int(r) - 0x4B400000;
    float f = y - (r - 12582912.0f);
    float p = 1.33978852e-3f;
    p = fmaf(p, f, 9.61843737e-3f);
    p = fmaf(p, f, 5.55033247e-2f);
    p = fmaf(p, f, 2.40226479e-1f);
    p = fmaf(p, f, 6.93147203e-1f);
    p = fmaf(p, f, 1.0f);
    return __int_as_float(__float_as_int(p) + (n << 23));
}

// ===========================================================================
// Tensor-core flash attention (split-precision bf16 mma).
// CTA = 128 q rows (8 warps x 16 rows), K/V tiles = 64 keys.
// smem: kh|kl|vh|vl as bf16 [64][56] (pitch 112B), + smadd[64].
// Q staged once (fp32, aliases the K/V area), folded scale, split into frags.
// S-fragments reused directly as P A-fragments for PV (FA-2 identity).
// V B-fragments via ldmatrix.x2.trans of [key][d] rows.
// ===========================================================================
#define KV_PITCH 112          // bytes per bf16 row (56 elems)
#define SM_KH 0
#define SM_KL 7168
#define SM_VH 14336
#define SM_VL 21504
#define SM_MADD 28672

__global__ __launch_bounds__(256, 1)
void attn_mma_kernel(const float* __restrict__ Q, const float* __restrict__ K,
                     const float* __restrict__ V, const float* __restrict__ mask,
                     float* __restrict__ ctx)
{
    __shared__ __align__(16) char sbuf[28672 + 256];
    const uint32_t sb = smem_u32(sbuf);

    const int tid  = threadIdx.x;
    const int wid  = tid >> 5;
    const int lane = tid & 31;
    const int g    = lane >> 2;
    const int tc   = lane & 3;

    const int qblk = (int)gridDim.x - 1 - (int)blockIdx.x;  // big CTAs first
    const int q0 = qblk * 128;
    const int bh = blockIdx.y;
    const int b = bh >> 4;
    const int h = bh & 15;
    const float scale = 0.14433756729740643f;   // 1/sqrt(48)

    // ---- stage Q (fp32) into smem (aliases K/V area), build scaled hi/lo frags
    {
        const float4* qg = (const float4*)(Q + ((size_t)bh * T_SZ + q0) * D_SZ);
        float4* qs4 = (float4*)sbuf;
        #pragma unroll
        for (int u = 0; u < 6; ++u) qs4[tid + u * 256] = qg[tid + u * 256];
    }
    __syncthreads();

    uint32_t qhi[3][4], qlo[3][4];
    {
        const float* qs = (const float*)sbuf;
        const int qr0 = wid * 16 + g;
        #pragma unroll
        for (int ks = 0; ks < 3; ++ks)
            #pragma unroll
            for (int hh = 0; hh < 2; ++hh) {
                int d0 = ks * 16 + hh * 8 + 2 * tc;
                float x0 = qs[qr0 * 48 + d0] * scale;
                float x1 = qs[qr0 * 48 + d0 + 1] * scale;
                float y0 = qs[(qr0 + 8) * 48 + d0] * scale;
                float y1 = qs[(qr0 + 8) * 48 + d0 + 1] * scale;
                pack_pair(qhi[ks][hh * 2],     qlo[ks][hh * 2],     x0, x1);
                pack_pair(qhi[ks][hh * 2 + 1], qlo[ks][hh * 2 + 1], y0, y1);
            }
    }
    __syncthreads();

    float oacc[6][4];
    #pragma unroll
    for (int i = 0; i < 6; ++i)
        #pragma unroll
        for (int j = 0; j < 4; ++j) oacc[i][j] = 0.0f;
    float mrow0 = -1e30f, mrow1 = -1e30f, rs0 = 0.0f, rs1 = 0.0f;

    const int rowg0 = q0 + wid * 16 + g;
    const int rowg1 = rowg0 + 8;
    const int ntiles = qblk * 2 + 2;

    // per-warp ldmatrix row base (lane&15 selects key within 16-chunk)
    const uint32_t vrow_h = sb + SM_VH + (uint32_t)((lane & 15) * KV_PITCH);
    const uint32_t vrow_l = sb + SM_VL + (uint32_t)((lane & 15) * KV_PITCH);

    for (int tile = 0; tile < ntiles; ++tile) {
        const int j0 = tile * 64;
        // ---- load K,V tile, convert to bf16 hi/lo
        {
            const float4* kg = (const float4*)(K + ((size_t)bh * T_SZ + j0) * D_SZ);
            const float4* vg = (const float4*)(V + ((size_t)bh * T_SZ + j0) * D_SZ);
            #pragma unroll
            for (int u = 0; u < 3; ++u) {
                int idx = tid + u * 256;          // 768 float4 per tensor
                int key = idx / 12;
                int dq  = idx - key * 12;
                uint32_t so = (uint32_t)(key * KV_PITCH + dq * 8);
                uint2 hh, ll;
                convert4(kg[idx], hh, ll);
                *(uint2*)(sbuf + SM_KH + so) = hh;
                *(uint2*)(sbuf + SM_KL + so) = ll;
                convert4(vg[idx], hh, ll);
                *(uint2*)(sbuf + SM_VH + so) = hh;
                *(uint2*)(sbuf + SM_VL + so) = ll;
            }
            if (tid < 64)
                ((float*)(sbuf + SM_MADD))[tid] =
                    (1.0f - mask[b * T_SZ + j0 + tid]) * -10000.0f;
        }
        __syncthreads();

        // ---- S = Qs * K^T  (split precision, 8 key-octets)
        float sfr[8][4];
        #pragma unroll
        for (int nt = 0; nt < 8; ++nt) {
            sfr[nt][0] = sfr[nt][1] = sfr[nt][2] = sfr[nt][3] = 0.0f;
            const char* kb  = sbuf + SM_KH + (nt * 8 + g) * KV_PITCH + tc * 4;
            const char* kbl = sbuf + SM_KL + (nt * 8 + g) * KV_PITCH + tc * 4;
            #pragma unroll
            for (int ks = 0; ks < 3; ++ks) {
                uint32_t bh2[2], bl2[2];
                bh2[0] = *(const uint32_t*)(kb + ks * 32);
                bh2[1] = *(const uint32_t*)(kb + ks * 32 + 16);
                bl2[0] = *(const uint32_t*)(kbl + ks * 32);
                bl2[1] = *(const uint32_t*)(kbl + ks * 32 + 16);
                mma_bf16(sfr[nt], qhi[ks], bh2);
                mma_bf16(sfr[nt], qhi[ks], bl2);
                mma_bf16(sfr[nt], qlo[ks], bh2);
            }
        }

        // ---- masks
        const float* smadd = (const float*)(sbuf + SM_MADD);
        const bool needmask = (tile >= ntiles - 2);
        #pragma unroll
        for (int nt = 0; nt < 8; ++nt) {
            float sa0 = smadd[nt * 8 + 2 * tc];
            float sa1 = smadd[nt * 8 + 2 * tc + 1];
            sfr[nt][0] += sa0; sfr[nt][1] += sa1;
            sfr[nt][2] += sa0; sfr[nt][3] += sa1;
            if (needmask) {
                int c0i = j0 + nt * 8 + 2 * tc;
                int c1i = c0i + 1;
                if (c0i > rowg0) sfr[nt][0] = -1e30f;
                if (c1i > rowg0) sfr[nt][1] = -1e30f;
                if (c0i > rowg1) sfr[nt][2] = -1e30f;
                if (c1i > rowg1) sfr[nt][3] = -1e30f;
            }
        }

        // ---- online softmax
        float cm0 = -1e30f, cm1 = -1e30f;
        #pragma unroll
        for (int nt = 0; nt < 8; ++nt) {
            cm0 = fmaxf(cm0, fmaxf(sfr[nt][0], sfr[nt][1]));
            cm1 = fmaxf(cm1, fmaxf(sfr[nt][2], sfr[nt][3]));
        }
        cm0 = fmaxf(cm0, __shfl_xor_sync(0xffffffffu, cm0, 1));
        cm0 = fmaxf(cm0, __shfl_xor_sync(0xffffffffu, cm0, 2));
        cm1 = fmaxf(cm1, __shfl_xor_sync(0xffffffffu, cm1, 1));
        cm1 = fmaxf(cm1, __shfl_xor_sync(0xffffffffu, cm1, 2));
        float mn0 = fmaxf(mrow0, cm0), mn1 = fmaxf(mrow1, cm1);
        float al0 = fast_exp(mrow0 - mn0), al1 = fast_exp(mrow1 - mn1);
        mrow0 = mn0; mrow1 = mn1;
        rs0 *= al0; rs1 *= al1;
        #pragma unroll
        for (int ntd = 0; ntd < 6; ++ntd) {
            oacc[ntd][0] *= al0; oacc[ntd][1] *= al0;
            oacc[ntd][2] *= al1; oacc[ntd][3] *= al1;
        }
        #pragma unroll
        for (int nt = 0; nt < 8; ++nt) {
            float p0 = fast_exp(sfr[nt][0] - mn0);
            float p1 = fast_exp(sfr[nt][1] - mn0);
            float p2 = fast_exp(sfr[nt][2] - mn1);
            float p3 = fast_exp(sfr[nt][3] - mn1);
            rs0 += p0 + p1; rs1 += p2 + p3;
            sfr[nt][0] = p0; sfr[nt][1] = p1;
            sfr[nt][2] = p2; sfr[nt][3] = p3;
        }

        // ---- O += P * V  (P frags from S frags; V via ldmatrix.trans)
        #pragma unroll
        for (int ks = 0; ks < 4; ++ks) {
            uint32_t aph[4], apl[4];
            pack_pair(aph[0], apl[0], sfr[2 * ks][0],     sfr[2 * ks][1]);
            pack_pair(aph[1], apl[1], sfr[2 * ks][2],     sfr[2 * ks][3]);
            pack_pair(aph[2], apl[2], sfr[2 * ks + 1][0], sfr[2 * ks + 1][1]);
            pack_pair(aph[3], apl[3], sfr[2 * ks + 1][2], sfr[2 * ks + 1][3]);
            const uint32_t rh = vrow_h + (uint32_t)(ks * 16 * KV_PITCH);
            const uint32_t rl = vrow_l + (uint32_t)(ks * 16 * KV_PITCH);
            #pragma unroll
            for (int ntd = 0; ntd < 6; ++ntd) {
                uint32_t bvh[2], bvl[2];
                LDSM_X2_T(bvh[0], bvh[1], rh + ntd * 16);
                LDSM_X2_T(bvl[0], bvl[1], rl + ntd * 16);
                mma_bf16(oacc[ntd], aph, bvh);
                mma_bf16(oacc[ntd], aph, bvl);
                mma_bf16(oacc[ntd], apl, bvh);
            }
        }
        __syncthreads();
    }

    // ---- epilogue
    rs0 += __shfl_xor_sync(0xffffffffu, rs0, 1);
    rs0 += __shfl_xor_sync(0xffffffffu, rs0, 2);
    rs1 += __shfl_xor_sync(0xffffffffu, rs1, 1);
    rs1 += __shfl_xor_sync(0xffffffffu, rs1, 2);
    const float i0 = 1.0f / rs0, i1 = 1.0f / rs1;

    float* base0 = ctx + ((size_t)b * T_SZ + rowg0 - 0) * C_SZ + h * D_SZ;
    float* base1 = ctx + ((size_t)b * T_SZ + rowg1 - 0) * C_SZ + h * D_SZ;
    // rowg0 includes q0 (global row within batch b's T dimension)
    base0 = ctx + ((size_t)b * T_SZ + rowg0) * C_SZ + h * D_SZ;
    base1 = ctx + ((size_t)b * T_SZ + rowg1) * C_SZ + h * D_SZ;
    #pragma unroll
    for (int ntd = 0; ntd < 6; ++ntd) {
        *(float2*)(base0 + ntd * 8 + 2 * tc) = make_float2(oacc[ntd][0] * i0, oacc[ntd][1] * i0);
        *(float2*)(base1 + ntd * 8 + 2 * tc) = make_float2(oacc[ntd][2] * i1, oacc[ntd][3] * i1);
    }
}

// ---------------------------------------------------------------------------
extern "C" void kernel_launch(void* const* d_in, const int* in_sizes, int n_in,
                              void* d_out, int out_size)
{
    const float* hs    = (const float*)d_in[0];
    const float* amask = (const float*)d_in[1];
    const float* Wq = (const float*)d_in[2]; const float* bq = (const float*)d_in[3];
    const float* Wk = (const float*)d_in[4]; const float* bk = (const float*)d_in[5];
    const float* Wv = (const float*)d_in[6]; const float* bv = (const float*)d_in[7];
    const float* Wo = (const float*)d_in[8]; const float* bo = (const float*)d_in[9];
    float* out = (float*)d_out;

    float *q_ptr, *k_ptr, *v_ptr, *ctx_ptr;
    cudaGetSymbolAddress((void**)&q_ptr,   g_q);
    cudaGetSymbolAddress((void**)&k_ptr,   g_k);
    cudaGetSymbolAddress((void**)&v_ptr,   g_v);
    cudaGetSymbolAddress((void**)&ctx_ptr, g_ctx);

    // 1. Fused QKV projections -> head-split layouts (tensor cores)
    dim3 g1(C_SZ / 128, M_SZ / 128, 3);
    gemm_mma_kernel<true><<<g1, 256>>>(hs, Wq, Wk, Wv, bq, bk, bv,
                                       q_ptr, k_ptr, v_ptr);

    // 2. RoPE in place on Q, K
    const int rope_total = B_SZ * H_SZ * T_SZ * (D_SZ / 2);
    rope_kernel<<<(rope_total + 255) / 256, 256>>>(q_ptr, k_ptr);

    // 3. Causal flash attention on tensor cores -> ctx [M, C]
    attn_mma_kernel<<<dim3(T_SZ / 128, B_SZ * H_SZ), 256>>>(q_ptr, k_ptr, v_ptr,
                                                            amask, ctx_ptr);

    // 4. Output projection -> d_out (tensor cores)
    dim3 g4(C_SZ / 128, M_SZ / 128, 1);
    gemm_mma_kernel<false><<<g4, 256>>>(ctx_ptr, Wo, Wo, Wo, bo, bo, bo,
                                        out, out, out);
}

// round 12
// speedup vs baseline: 2.0552x; 1.0173x over previous
#include <cuda_runtime.h>
#include <cstdint>
#include <math.h>

#define B_SZ 4
#define T_SZ 2048
#define C_SZ 768
#define H_SZ 16
#define D_SZ 48
#define M_SZ (B_SZ * T_SZ)          // 8192

// Scratch (device globals: allocation-free rule)
__device__ float g_q[B_SZ * H_SZ * T_SZ * D_SZ];   // [bh][t][d]
__device__ float g_k[B_SZ * H_SZ * T_SZ * D_SZ];
__device__ float g_v[B_SZ * H_SZ * T_SZ * D_SZ];
__device__ float g_ctx[B_SZ * T_SZ * C_SZ];        // [b*t][c]

// ===========================================================================
// mma.sync bf16 (baseline PTX -> HMMA SASS on sm_103)
// ===========================================================================
__device__ __forceinline__ void mma_bf16(float* d, const uint32_t* a, const uint32_t* b)
{
    asm volatile(
        "mma.sync.aligned.m16n8k16.row.col.f32.bf16.bf16.f32 "
        "{%0,%1,%2,%3}, {%4,%5,%6,%7}, {%8,%9}, {%0,%1,%2,%3};"
        : "+f"(d[0]), "+f"(d[1]), "+f"(d[2]), "+f"(d[3])
        : "r"(a[0]), "r"(a[1]), "r"(a[2]), "r"(a[3]), "r"(b[0]), "r"(b[1]));
}

__device__ __forceinline__ uint32_t smem_u32(const void* p) {
    uint32_t a;
    asm("{ .reg .u64 t; cvta.to.shared.u64 t, %1; cvt.u32.u64 %0, t; }" : "=r"(a) : "l"(p));
    return a;
}

#define LDSM_X2_T(r0, r1, addr) \
    asm volatile("ldmatrix.sync.aligned.m8n8.x2.trans.shared.b16 {%0,%1}, [%2];" \
                 : "=r"(r0), "=r"(r1) : "r"(addr))

// split fp32 pair -> bf16x2 hi + bf16x2 lo
__device__ __forceinline__ void pack_pair(uint32_t& hi, uint32_t& lo, float x0, float x1)
{
    asm("cvt.rn.bf16x2.f32 %0, %1, %2;" : "=r"(hi) : "f"(x1), "f"(x0));
    float r0 = x0 - __uint_as_float(hi << 16);
    float r1 = x1 - __uint_as_float(hi & 0xFFFF0000u);
    asm("cvt.rn.bf16x2.f32 %0, %1, %2;" : "=r"(lo) : "f"(r1), "f"(r0));
}

__device__ __forceinline__ void convert4(float4 v, uint2& h, uint2& l)
{
    uint32_t h0, h1, l0, l1;
    asm("cvt.rn.bf16x2.f32 %0, %1, %2;" : "=r"(h0) : "f"(v.y), "f"(v.x));
    asm("cvt.rn.bf16x2.f32 %0, %1, %2;" : "=r"(h1) : "f"(v.w), "f"(v.z));
    float r0 = v.x - __uint_as_float(h0 << 16);
    float r1 = v.y - __uint_as_float(h0 & 0xFFFF0000u);
    float r2 = v.z - __uint_as_float(h1 << 16);
    float r3 = v.w - __uint_as_float(h1 & 0xFFFF0000u);
    asm("cvt.rn.bf16x2.f32 %0, %1, %2;" : "=r"(l0) : "f"(r1), "f"(r0));
    asm("cvt.rn.bf16x2.f32 %0, %1, %2;" : "=r"(l1) : "f"(r3), "f"(r2));
    h = make_uint2(h0, h1);
    l = make_uint2(l0, l1);
}

// ===========================================================================
// Split-precision bf16 tensor-core GEMM: out = A*W^T + bias
// Double-buffered smem (2 stages x 4 tiles x [128][40] bf16, 80KB dynamic).
// One __syncthreads per K-block; convert of stage s+1 overlaps MMAs on s.
// ===========================================================================
#define NKB (C_SZ / 32)
#define GT_TILE 10240          // one tile: 128 rows x 80 B
#define GT_STAGE 40960         // 4 tiles

template<bool SPLIT>
__global__ __launch_bounds__(256, 1)
void gemm_mma_kernel(const float* __restrict__ A,
                     const float* __restrict__ W0, const float* __restrict__ W1, const float* __restrict__ W2,
                     const float* __restrict__ b0, const float* __restrict__ b1, const float* __restrict__ b2,
                     float* o0, float* o1, float* o2)
{
    const float* W; const float* bias; float* O;
    if (blockIdx.z == 0)      { W = W0; bias = b0; O = o0; }
    else if (blockIdx.z == 1) { W = W1; bias = b1; O = o1; }
    else                      { W = W2; bias = b2; O = o2; }

    extern __shared__ __align__(16) char dsm[];   // 2 * GT_STAGE

    const int tid  = threadIdx.x;
    const int wid  = tid >> 5;
    const int lane = tid & 31;
    const int warp_m = wid & 1;
    const int warp_n = wid >> 1;
    const int m0 = blockIdx.y * 128;
    const int n0 = blockIdx.x * 128;

    const int row = tid >> 1;
    const int hf  = tid & 1;
    const float* Asrc = A + (size_t)(m0 + row) * C_SZ + hf * 16;
    const float* Bsrc = W + (size_t)(n0 + row) * C_SZ + hf * 16;

    float4 pa[4], pb[4];

    auto fetch = [&](int kb) {
        #pragma unroll
        for (int q = 0; q < 4; ++q) {
            pa[q] = *(const float4*)(Asrc + kb * 32 + q * 4);
            pb[q] = *(const float4*)(Bsrc + kb * 32 + q * 4);
        }
    };

    auto cvst = [&](int st) {
        char* base = dsm + st * GT_STAGE;
        #pragma unroll
        for (int q = 0; q < 4; ++q) {
            const uint32_t boff = (uint32_t)(row * 80 + (hf * 16 + q * 4) * 2);
            uint2 h, l;
            convert4(pa[q], h, l);
            *(uint2*)(base + boff)            = h;
            *(uint2*)(base + GT_TILE + boff)  = l;
            convert4(pb[q], h, l);
            *(uint2*)(base + 2 * GT_TILE + boff) = h;
            *(uint2*)(base + 3 * GT_TILE + boff) = l;
        }
    };

    float acc[16][4];
    #pragma unroll
    for (int i = 0; i < 16; ++i)
        #pragma unroll
        for (int j = 0; j < 4; ++j) acc[i][j] = 0.0f;

    const int g  = lane >> 2;
    const int tc = lane & 3;
    const uint32_t a_off = (uint32_t)((warp_m * 64 + g) * 80 + tc * 4);
    const uint32_t b_off = (uint32_t)((warp_n * 32 + g) * 80 + tc * 4);

    fetch(0);
    cvst(0);
    __syncthreads();

    for (int kb = 0; kb < NKB; ++kb) {
        const int st = kb & 1;
        const char* stage = dsm + st * GT_STAGE;
        if (kb + 1 < NKB) fetch(kb + 1);

        #pragma unroll
        for (int ks = 0; ks < 2; ++ks) {
            uint32_t ahi[4][4], alo[4][4], bhi[4][2], blo[4][2];
            #pragma unroll
            for (int mt = 0; mt < 4; ++mt) {
                const uint32_t o = a_off + (uint32_t)(mt * 16 * 80 + ks * 32);
                const char* ph = stage + o;
                const char* pl = stage + GT_TILE + o;
                ahi[mt][0] = *(const uint32_t*)ph;
                ahi[mt][1] = *(const uint32_t*)(ph + 8 * 80);
                ahi[mt][2] = *(const uint32_t*)(ph + 16);
                ahi[mt][3] = *(const uint32_t*)(ph + 8 * 80 + 16);
                alo[mt][0] = *(const uint32_t*)pl;
                alo[mt][1] = *(const uint32_t*)(pl + 8 * 80);
                alo[mt][2] = *(const uint32_t*)(pl + 16);
                alo[mt][3] = *(const uint32_t*)(pl + 8 * 80 + 16);
            }
            #pragma unroll
            for (int nt = 0; nt < 4; ++nt) {
                const uint32_t o = b_off + (uint32_t)(nt * 8 * 80 + ks * 32);
                const char* ph = stage + 2 * GT_TILE + o;
                const char* pl = stage + 3 * GT_TILE + o;
                bhi[nt][0] = *(const uint32_t*)ph;
                bhi[nt][1] = *(const uint32_t*)(ph + 16);
                blo[nt][0] = *(const uint32_t*)pl;
                blo[nt][1] = *(const uint32_t*)(pl + 16);
            }
            #pragma unroll
            for (int mt = 0; mt < 4; ++mt)
                #pragma unroll
                for (int nt = 0; nt < 4; ++nt) {
                    mma_bf16(acc[mt * 4 + nt], ahi[mt], bhi[nt]);
                    mma_bf16(acc[mt * 4 + nt], ahi[mt], blo[nt]);
                    mma_bf16(acc[mt * 4 + nt], alo[mt], bhi[nt]);
                }
        }
        if (kb + 1 < NKB) cvst((kb + 1) & 1);
        __syncthreads();
    }

    #pragma unroll
    for (int mt = 0; mt < 4; ++mt) {
        const int rm = m0 + warp_m * 64 + mt * 16 + g;
        #pragma unroll
        for (int nt = 0; nt < 4; ++nt) {
            const int n = n0 + warp_n * 32 + nt * 8 + tc * 2;
            const float* ac = acc[mt * 4 + nt];
            float bv0 = __ldg(bias + n), bv1 = __ldg(bias + n + 1);
            if (SPLIT) {
                #pragma unroll
                for (int e = 0; e < 4; ++e) {
                    int m = rm + (e >> 1) * 8;
                    int nn = n + (e & 1);
                    float v = ac[e] + ((e & 1) ? bv1 : bv0);
                    int b = m >> 11;
                    int t = m & (T_SZ - 1);
                    int h = nn / D_SZ;
                    int d = nn - h * D_SZ;
                    O[(((size_t)(b * H_SZ + h)) * T_SZ + t) * D_SZ + d] = v;
                }
            } else {
                *(float2*)(O + (size_t)rm * C_SZ + n)       = make_float2(ac[0] + bv0, ac[1] + bv1);
                *(float2*)(O + (size_t)(rm + 8) * C_SZ + n) = make_float2(ac[2] + bv0, ac[3] + bv1);
            }
        }
    }
}

// ---------------------------------------------------------------------------
// RoPE, in-place on Q and K ([bh][t][48] layout)
// ---------------------------------------------------------------------------
__global__ __launch_bounds__(256)
void rope_kernel(float* __restrict__ q, float* __restrict__ k)
{
    const int total = B_SZ * H_SZ * T_SZ * (D_SZ / 2);
    int idx = blockIdx.x * blockDim.x + threadIdx.x;
    if (idx >= total) return;
    int j   = idx % (D_SZ / 2);
    int row = idx / (D_SZ / 2);
    int t   = row & (T_SZ - 1);

    float inv = (float)exp(-log(10000.0) * (double)j / 24.0);
    float ang = (float)t * inv;
    float s, c;
    sincosf(ang, &s, &c);

    float* qp = q + (size_t)row * D_SZ;
    float q1 = qp[j], q2 = qp[j + 24];
    qp[j]      = q1 * c - q2 * s;
    qp[j + 24] = q2 * c + q1 * s;

    float* kp = k + (size_t)row * D_SZ;
    float k1 = kp[j], k2 = kp[j + 24];
    kp[j]      = k1 * c - k2 * s;
    kp[j + 24] = k2 * c + k1 * s;
}

// ===========================================================================
// Tensor-core flash attention (split-precision bf16 mma).
// CTA = 128 q rows (8 warps x 16 rows). Outer tile = 128 keys (one smem load,
// one barrier pair), processed as 2 x 64-key inner passes.
// exp on MUFU (__expf) — tensor pipe does matmuls, FMA pipe freed.
// smem (dynamic, 58KB): kh|kl|vh|vl bf16 [128][56] pitch 112B + madd[128].
// ===========================================================================
#define KV_PITCH 112
#define SM_KH 0
#define SM_KL 14336
#define SM_VH 28672
#define SM_VL 43008
#define SM_MADD 57344
#define ATT_SMEM (57344 + 512 + 128)

__global__ __launch_bounds__(256, 1)
void attn_mma_kernel(const float* __restrict__ Q, const float* __restrict__ K,
                     const float* __restrict__ V, const float* __restrict__ mask,
                     float* __restrict__ ctx)
{
    extern __shared__ __align__(16) char sbuf[];
    const uint32_t sb = smem_u32(sbuf);

    const int tid  = threadIdx.x;
    const int wid  = tid >> 5;
    const int lane = tid & 31;
    const int g    = lane >> 2;
    const int tc   = lane & 3;

    const int qblk = (int)gridDim.x - 1 - (int)blockIdx.x;  // big CTAs first
    const int q0 = qblk * 128;
    const int bh = blockIdx.y;
    const int b = bh >> 4;
    const int h = bh & 15;
    const float scale = 0.14433756729740643f;   // 1/sqrt(48)

    // ---- stage Q (fp32) into smem (aliases K/V area), build scaled hi/lo frags
    {
        const float4* qg = (const float4*)(Q + ((size_t)bh * T_SZ + q0) * D_SZ);
        float4* qs4 = (float4*)sbuf;
        #pragma unroll
        for (int u = 0; u < 6; ++u) qs4[tid + u * 256] = qg[tid + u * 256];
    }
    __syncthreads();

    uint32_t qhi[3][4], qlo[3][4];
    {
        const float* qs = (const float*)sbuf;
        const int qr0 = wid * 16 + g;
        #pragma unroll
        for (int ks = 0; ks < 3; ++ks)
            #pragma unroll
            for (int hh = 0; hh < 2; ++hh) {
                int d0 = ks * 16 + hh * 8 + 2 * tc;
                float x0 = qs[qr0 * 48 + d0] * scale;
                float x1 = qs[qr0 * 48 + d0 + 1] * scale;
                float y0 = qs[(qr0 + 8) * 48 + d0] * scale;
                float y1 = qs[(qr0 + 8) * 48 + d0 + 1] * scale;
                pack_pair(qhi[ks][hh * 2],     qlo[ks][hh * 2],     x0, x1);
                pack_pair(qhi[ks][hh * 2 + 1], qlo[ks][hh * 2 + 1], y0, y1);
            }
    }
    __syncthreads();

    float oacc[6][4];
    #pragma unroll
    for (int i = 0; i < 6; ++i)
        #pragma unroll
        for (int j = 0; j < 4; ++j) oacc[i][j] = 0.0f;
    float mrow0 = -1e30f, mrow1 = -1e30f, rs0 = 0.0f, rs1 = 0.0f;

    const int rowg0 = q0 + wid * 16 + g;
    const int rowg1 = rowg0 + 8;
    const int ntiles = qblk + 1;          // 128-key tiles covering 0..q0+127

    for (int tile = 0; tile < ntiles; ++tile) {
        const int j0 = tile * 128;
        // ---- load 128 keys of K,V; convert to bf16 hi/lo
        {
            const float4* kg = (const float4*)(K + ((size_t)bh * T_SZ + j0) * D_SZ);
            const float4* vg = (const float4*)(V + ((size_t)bh * T_SZ + j0) * D_SZ);
            #pragma unroll
            for (int u = 0; u < 6; ++u) {
                int idx = tid + u * 256;          // 1536 float4 per tensor
                int key = idx / 12;
                int dq  = idx - key * 12;
                uint32_t so = (uint32_t)(key * KV_PITCH + dq * 8);
                uint2 hh, ll;
                convert4(kg[idx], hh, ll);
                *(uint2*)(sbuf + SM_KH + so) = hh;
                *(uint2*)(sbuf + SM_KL + so) = ll;
                convert4(vg[idx], hh, ll);
                *(uint2*)(sbuf + SM_VH + so) = hh;
                *(uint2*)(sbuf + SM_VL + so) = ll;
            }
            if (tid < 128)
                ((float*)(sbuf + SM_MADD))[tid] =
                    (1.0f - mask[b * T_SZ + j0 + tid]) * -10000.0f;
        }
        __syncthreads();

        const bool needmask = (tile == ntiles - 1);

        #pragma unroll 1
        for (int half = 0; half < 2; ++half) {
            const int jh = j0 + half * 64;

            // ---- S = Qs * K^T  (split precision, 8 key-octets)
            float sfr[8][4];
            #pragma unroll
            for (int nt = 0; nt < 8; ++nt) {
                sfr[nt][0] = sfr[nt][1] = sfr[nt][2] = sfr[nt][3] = 0.0f;
                const char* kb  = sbuf + SM_KH + (half * 64 + nt * 8 + g) * KV_PITCH + tc * 4;
                const char* kbl = sbuf + SM_KL + (half * 64 + nt * 8 + g) * KV_PITCH + tc * 4;
                #pragma unroll
                for (int ks = 0; ks < 3; ++ks) {
                    uint32_t bh2[2], bl2[2];
                    bh2[0] = *(const uint32_t*)(kb + ks * 32);
                    bh2[1] = *(const uint32_t*)(kb + ks * 32 + 16);
                    bl2[0] = *(const uint32_t*)(kbl + ks * 32);
                    bl2[1] = *(const uint32_t*)(kbl + ks * 32 + 16);
                    mma_bf16(sfr[nt], qhi[ks], bh2);
                    mma_bf16(sfr[nt], qhi[ks], bl2);
                    mma_bf16(sfr[nt], qlo[ks], bh2);
                }
            }

            // ---- masks
            const float* smadd = (const float*)(sbuf + SM_MADD) + half * 64;
            #pragma unroll
            for (int nt = 0; nt < 8; ++nt) {
                float sa0 = smadd[nt * 8 + 2 * tc];
                float sa1 = smadd[nt * 8 + 2 * tc + 1];
                sfr[nt][0] += sa0; sfr[nt][1] += sa1;
                sfr[nt][2] += sa0; sfr[nt][3] += sa1;
                if (needmask) {
                    int c0i = jh + nt * 8 + 2 * tc;
                    int c1i = c0i + 1;
                    if (c0i > rowg0) sfr[nt][0] = -1e30f;
                    if (c1i > rowg0) sfr[nt][1] = -1e30f;
                    if (c0i > rowg1) sfr[nt][2] = -1e30f;
                    if (c1i > rowg1) sfr[nt][3] = -1e30f;
                }
            }

            // ---- online softmax (exp on MUFU)
            float cm0 = -1e30f, cm1 = -1e30f;
            #pragma unroll
            for (int nt = 0; nt < 8; ++nt) {
                cm0 = fmaxf(cm0, fmaxf(sfr[nt][0], sfr[nt][1]));
                cm1 = fmaxf(cm1, fmaxf(sfr[nt][2], sfr[nt][3]));
            }
            cm0 = fmaxf(cm0, __shfl_xor_sync(0xffffffffu, cm0, 1));
            cm0 = fmaxf(cm0, __shfl_xor_sync(0xffffffffu, cm0, 2));
            cm1 = fmaxf(cm1, __shfl_xor_sync(0xffffffffu, cm1, 1));
            cm1 = fmaxf(cm1, __shfl_xor_sync(0xffffffffu, cm1, 2));
            float mn0 = fmaxf(mrow0, cm0), mn1 = fmaxf(mrow1, cm1);
            float al0 = __expf(mrow0 - mn0), al1 = __expf(mrow1 - mn1);
            mrow0 = mn0; mrow1 = mn1;
            rs0 *= al0; rs1 *= al1;
            #pragma unroll
            for (int ntd = 0; ntd < 6; ++ntd) {
                oacc[ntd][0] *= al0; oacc[ntd][1] *= al0;
                oacc[ntd][2] *= al1; oacc[ntd][3] *= al1;
            }
            #pragma unroll
            for (int nt = 0; nt < 8; ++nt) {
                float p0 = __expf(sfr[nt][0] - mn0);
                float p1 = __expf(sfr[nt][1] - mn0);
                float p2 = __expf(sfr[nt][2] - mn1);
                float p3 = __expf(sfr[nt][3] - mn1);
                rs0 += p0 + p1; rs1 += p2 + p3;
                sfr[nt][0] = p0; sfr[nt][1] = p1;
                sfr[nt][2] = p2; sfr[nt][3] = p3;
            }

            // ---- O += P * V  (P frags from S frags; V via ldmatrix.trans)
            const uint32_t vrow_h = sb + SM_VH +
                (uint32_t)((half * 64 + (lane & 15)) * KV_PITCH);
            const uint32_t vrow_l = vrow_h + (uint32_t)(SM_VL - SM_VH);
            #pragma unroll
            for (int ks = 0; ks < 4; ++ks) {
                uint32_t aph[4], apl[4];
                pack_pair(aph[0], apl[0], sfr[2 * ks][0],     sfr[2 * ks][1]);
                pack_pair(aph[1], apl[1], sfr[2 * ks][2],     sfr[2 * ks][3]);
                pack_pair(aph[2], apl[2], sfr[2 * ks + 1][0], sfr[2 * ks + 1][1]);
                pack_pair(aph[3], apl[3], sfr[2 * ks + 1][2], sfr[2 * ks + 1][3]);
                const uint32_t rh = vrow_h + (uint32_t)(ks * 16 * KV_PITCH);
                const uint32_t rl = vrow_l + (uint32_t)(ks * 16 * KV_PITCH);
                #pragma unroll
                for (int ntd = 0; ntd < 6; ++ntd) {
                    uint32_t bvh[2], bvl[2];
                    LDSM_X2_T(bvh[0], bvh[1], rh + ntd * 16);
                    LDSM_X2_T(bvl[0], bvl[1], rl + ntd * 16);
                    mma_bf16(oacc[ntd], aph, bvh);
                    mma_bf16(oacc[ntd], aph, bvl);
                    mma_bf16(oacc[ntd], apl, bvh);
                }
            }
        }
        __syncthreads();
    }

    // ---- epilogue
    rs0 += __shfl_xor_sync(0xffffffffu, rs0, 1);
    rs0 += __shfl_xor_sync(0xffffffffu, rs0, 2);
    rs1 += __shfl_xor_sync(0xffffffffu, rs1, 1);
    rs1 += __shfl_xor_sync(0xffffffffu, rs1, 2);
    const float i0 = 1.0f / rs0, i1 = 1.0f / rs1;

    float* base0 = ctx + ((size_t)b * T_SZ + rowg0) * C_SZ + h * D_SZ;
    float* base1 = ctx + ((size_t)b * T_SZ + rowg1) * C_SZ + h * D_SZ;
    #pragma unroll
    for (int ntd = 0; ntd < 6; ++ntd) {
        *(float2*)(base0 + ntd * 8 + 2 * tc) = make_float2(oacc[ntd][0] * i0, oacc[ntd][1] * i0);
        *(float2*)(base1 + ntd * 8 + 2 * tc) = make_float2(oacc[ntd][2] * i1, oacc[ntd][3] * i1);
    }
}

// ---------------------------------------------------------------------------
extern "C" void kernel_launch(void* const* d_in, const int* in_sizes, int n_in,
                              void* d_out, int out_size)
{
    const float* hs    = (const float*)d_in[0];
    const float* amask = (const float*)d_in[1];
    const float* Wq = (const float*)d_in[2]; const float* bq = (const float*)d_in[3];
    const float* Wk = (const float*)d_in[4]; const float* bk = (const float*)d_in[5];
    const float* Wv = (const float*)d_in[6]; const float* bv = (const float*)d_in[7];
    const float* Wo = (const float*)d_in[8]; const float* bo = (const float*)d_in[9];
    float* out = (float*)d_out;

    float *q_ptr, *k_ptr, *v_ptr, *ctx_ptr;
    cudaGetSymbolAddress((void**)&q_ptr,   g_q);
    cudaGetSymbolAddress((void**)&k_ptr,   g_k);
    cudaGetSymbolAddress((void**)&v_ptr,   g_v);
    cudaGetSymbolAddress((void**)&ctx_ptr, g_ctx);

    const int gemm_smem = 2 * GT_STAGE;                  // 81920
    cudaFuncSetAttribute(gemm_mma_kernel<true>,  cudaFuncAttributeMaxDynamicSharedMemorySize, gemm_smem);
    cudaFuncSetAttribute(gemm_mma_kernel<false>, cudaFuncAttributeMaxDynamicSharedMemorySize, gemm_smem);
    cudaFuncSetAttribute(attn_mma_kernel, cudaFuncAttributeMaxDynamicSharedMemorySize, ATT_SMEM);

    // 1. Fused QKV projections -> head-split layouts (tensor cores)
    dim3 g1(C_SZ / 128, M_SZ / 128, 3);
    gemm_mma_kernel<true><<<g1, 256, gemm_smem>>>(hs, Wq, Wk, Wv, bq, bk, bv,
                                                  q_ptr, k_ptr, v_ptr);

    // 2. RoPE in place on Q, K
    const int rope_total = B_SZ * H_SZ * T_SZ * (D_SZ / 2);
    rope_kernel<<<(rope_total + 255) / 256, 256>>>(q_ptr, k_ptr);

    // 3. Causal flash attention on tensor cores -> ctx [M, C]
    attn_mma_kernel<<<dim3(T_SZ / 128, B_SZ * H_SZ), 256, ATT_SMEM>>>(
        q_ptr, k_ptr, v_ptr, amask, ctx_ptr);

    // 4. Output projection -> d_out (tensor cores)
    dim3 g4(C_SZ / 128, M_SZ / 128, 1);
    gemm_mma_kernel<false><<<g4, 256, gemm_smem>>>(ctx_ptr, Wo, Wo, Wo, bo, bo, bo,
                                                   out, out, out);
}